// round 12
// baseline (speedup 1.0000x reference)
#include <cuda_runtime.h>
#include <cuda_bf16.h>
#include <cstdint>

// TELIF: temporal-encoded LIF spiking neuron scan.
// tx: [T, B, N] f32, TE: [N, T] f32 -> ty: [T, B, N] f32.
//
// R12 = R11 (best: 53.4us total, scan 39.5us @ 69.4% DRAM) with the consumer
// widened to float4: 16 active lanes x 4 neurons each (lanes 16-31 exit).
// LDS 16x.64 -> 8x.128, STG 8x.64 -> 4x.128, ILP-4 LIF chains. Producers,
// mbarrier ring (STAGES=6, LAG=4), 1024-block geometry all unchanged.

#define T_STEPS 512
#define B_DIM   64
#define N_DIM   1024
#define BN      (B_DIM * N_DIM)

#define REST      0.0f
#define DECAY     0.2f
#define THRESHOLD 0.3f
#define BETA      0.02f

#define CHUNK    8                    // time steps per stage
#define NCHUNK   (T_STEPS / CHUNK)    // 64
#define STAGES   6
#define LAG      4                    // commit-group completion lag
#define HALVES   2                    // producer warps (32 neurons each)
#define BLKT     96                   // warps 0,1 = producers; warp 2 = consumer
#define GRID     (BN / 64)            // 1024 blocks, 64 neurons each

__device__ float g_te_t[T_STEPS * N_DIM];   // TE transposed to [T][N]

// ---------------------------------------------------------------------------
// Transpose TE [N, T] -> g_te_t [T, N]. 32x32 tiles, padded smem.
// ---------------------------------------------------------------------------
__global__ void telif_transpose_te(const float* __restrict__ TE) {
    __shared__ float tile[32][33];
    int n0 = blockIdx.x * 32;
    int t0 = blockIdx.y * 32;
    int lx = threadIdx.x;
    int ly = threadIdx.y;

#pragma unroll
    for (int i = 0; i < 32; i += 8)
        tile[ly + i][lx] = TE[(size_t)(n0 + ly + i) * T_STEPS + (t0 + lx)];
    __syncthreads();
#pragma unroll
    for (int i = 0; i < 32; i += 8)
        g_te_t[(size_t)(t0 + ly + i) * N_DIM + (n0 + lx)] = tile[lx][ly + i];
}

// ---------------------------------------------------------------------------
// PTX helpers
// ---------------------------------------------------------------------------
__device__ __forceinline__ uint32_t smem_u32(const void* p) {
    return (uint32_t)__cvta_generic_to_shared(p);
}
__device__ __forceinline__ void cp_async16(uint32_t saddr, const void* gptr) {
    asm volatile("cp.async.cg.shared.global [%0], [%1], 16;\n"
                 :: "r"(saddr), "l"(gptr));
}
__device__ __forceinline__ void cp_commit() {
    asm volatile("cp.async.commit_group;\n");
}
__device__ __forceinline__ void cp_wait_lag() {
    asm volatile("cp.async.wait_group 4;\n" ::: "memory");
}
__device__ __forceinline__ void cp_wait_all() {
    asm volatile("cp.async.wait_group 0;\n" ::: "memory");
}
__device__ __forceinline__ void mbar_init(uint32_t a, uint32_t cnt) {
    asm volatile("mbarrier.init.shared.b64 [%0], %1;\n" :: "r"(a), "r"(cnt) : "memory");
}
__device__ __forceinline__ void mbar_arrive(uint32_t a) {
    asm volatile("mbarrier.arrive.release.cta.shared::cta.b64 _, [%0];\n"
                 :: "r"(a) : "memory");
}
__device__ __forceinline__ void mbar_wait(uint32_t a, uint32_t phase) {
    uint32_t done;
    asm volatile(
        "{\n\t.reg .pred p;\n\t"
        "mbarrier.try_wait.parity.acquire.cta.shared::cta.b64 p, [%1], %2;\n\t"
        "selp.b32 %0, 1, 0, p;\n\t}"
        : "=r"(done) : "r"(a), "r"(phase) : "memory");
    if (!done) {
        asm volatile(
            "{\n\t.reg .pred P1;\n\t"
            "WL_%=:\n\t"
            "mbarrier.try_wait.parity.acquire.cta.shared::cta.b64 P1, [%0], %1;\n\t"
            "@P1 bra.uni WD_%=;\n\t"
            "bra.uni WL_%=;\n\t"
            "WD_%=:\n\t}"
            :: "r"(a), "r"(phase) : "memory");
    }
}

// ---------------------------------------------------------------------------
// Main scan: per block 64 neurons = 2 producer warps + 1 float4 consumer warp
// (16 active lanes, 4 neurons each).
// smem stage layout: [half][stage][arr(tx=0,te=1)][step][lane32]
// ---------------------------------------------------------------------------
__global__ void __launch_bounds__(BLKT, 7)
telif_scan(const float* __restrict__ tx, float* __restrict__ out) {
    __shared__ __align__(16) float stg[HALVES][STAGES][2][CHUNK][32];
    __shared__ __align__(8)  uint64_t mb_full[HALVES][STAGES];
    __shared__ __align__(8)  uint64_t mb_empty[HALVES][STAGES];

    const int tid  = threadIdx.x;
    const int wid  = tid >> 5;
    const int lane = tid & 31;
    const int blockbase = blockIdx.x * 64;        // first (b*N+n) of block

    if (tid == 0) {
#pragma unroll
        for (int h = 0; h < HALVES; h++)
#pragma unroll
            for (int s = 0; s < STAGES; s++) {
                mbar_init(smem_u32(&mb_full[h][s]), 32);   // producer warp arrives
                mbar_init(smem_u32(&mb_empty[h][s]), 16);  // 16 consumer lanes arrive
            }
    }
    __syncthreads();

    if (wid < HALVES) {
        // ------------------ producer warp (unchanged R8/R11 pump) ------------
        const int p = wid;
        const int pairbase = blockbase + p * 32;
        const float* txb = tx + pairbase;
        const float* teb = g_te_t + (pairbase & (N_DIM - 1));

        // cp.async split: k = lane + 32j -> step st = k>>3, seg = (k&7)*4.
        const int k0  = lane;
        const int k1  = lane + 32;
        const int st0 = k0 >> 3, sg0 = (k0 & 7) * 4;
        const int st1 = k1 >> 3, sg1 = (k1 & 7) * 4;

        int es = 0, eph = 1;     // empty-wait cursor
        int as = 0;              // full-arrive cursor (lags by LAG)

#pragma unroll 1
        for (int c = 0; c < NCHUNK; c++) {
            mbar_wait(smem_u32(&mb_empty[p][es]), eph);

            const float* ctx = txb + (size_t)(c * CHUNK) * BN;
            const float* cte = teb + (size_t)(c * CHUNK) * N_DIM;
            cp_async16(smem_u32(&stg[p][es][0][st0][sg0]), ctx + (size_t)st0 * BN + sg0);
            cp_async16(smem_u32(&stg[p][es][1][st0][sg0]), cte + (size_t)st0 * N_DIM + sg0);
            cp_async16(smem_u32(&stg[p][es][0][st1][sg1]), ctx + (size_t)st1 * BN + sg1);
            cp_async16(smem_u32(&stg[p][es][1][st1][sg1]), cte + (size_t)st1 * N_DIM + sg1);
            cp_commit();

            if (c >= LAG) {
                cp_wait_lag();                       // group c-LAG complete
                mbar_arrive(smem_u32(&mb_full[p][as]));
                if (++as == STAGES) as = 0;
            }
            if (++es == STAGES) { es = 0; eph ^= 1; }
        }
        // Tail: flush last LAG chunks.
        cp_wait_all();
#pragma unroll
        for (int r = 0; r < LAG; r++) {
            mbar_arrive(smem_u32(&mb_full[p][as]));
            if (++as == STAGES) as = 0;
        }
    } else if (lane < 16) {
        // -------------- consumer: 16 lanes x 4 neurons (float4) -------------
        // lane l -> neurons blockbase + 4l .. 4l+3; half h = l>>3.
        const int h  = lane >> 3;
        const int j4 = (4 * lane) & 31;
        float* op = out + blockbase + 4 * lane;     // 16B-aligned

        float4 v  = make_float4(REST, REST, REST, REST);
        float4 y  = make_float4(0.0f, 0.0f, 0.0f, 0.0f);
        float4 th = make_float4(THRESHOLD, THRESHOLD, THRESHOLD, THRESHOLD);

        int fs = 0, fph = 0;     // full-wait cursor

#pragma unroll 1
        for (int c = 0; c < NCHUNK; c++) {
            mbar_wait(smem_u32(&mb_full[0][fs]), fph);
            mbar_wait(smem_u32(&mb_full[1][fs]), fph);

            // Two 4-step sub-batches (keeps buffer regs at 32).
#pragma unroll
            for (int g = 0; g < 2; g++) {
                float4 xr[4], tr[4];
#pragma unroll
                for (int s = 0; s < 4; s++) {
                    xr[s] = *reinterpret_cast<const float4*>(&stg[h][fs][0][g * 4 + s][j4]);
                    tr[s] = *reinterpret_cast<const float4*>(&stg[h][fs][1][g * 4 + s][j4]);
                }
#pragma unroll
                for (int s = 0; s < 4; s++) {
                    th.x = th.x + v.x * tr[s].x - (th.x - THRESHOLD) * BETA;
                    th.y = th.y + v.y * tr[s].y - (th.y - THRESHOLD) * BETA;
                    th.z = th.z + v.z * tr[s].z - (th.z - THRESHOLD) * BETA;
                    th.w = th.w + v.w * tr[s].w - (th.w - THRESHOLD) * BETA;

                    v.x = v.x * DECAY * (1.0f - y.x) + xr[s].x;
                    v.y = v.y * DECAY * (1.0f - y.y) + xr[s].y;
                    v.z = v.z * DECAY * (1.0f - y.z) + xr[s].z;
                    v.w = v.w * DECAY * (1.0f - y.w) + xr[s].w;

                    y.x = (v.x > th.x) ? 1.0f : 0.0f;
                    y.y = (v.y > th.y) ? 1.0f : 0.0f;
                    y.z = (v.z > th.z) ? 1.0f : 0.0f;
                    y.w = (v.w > th.w) ? 1.0f : 0.0f;

                    *reinterpret_cast<float4*>(
                        op + (size_t)(c * CHUNK + g * 4 + s) * BN) = y;
                }
            }

            mbar_arrive(smem_u32(&mb_empty[0][fs]));
            mbar_arrive(smem_u32(&mb_empty[1][fs]));
            if (++fs == STAGES) { fs = 0; fph ^= 1; }
        }
    }
}

// ---------------------------------------------------------------------------
// Launch
// ---------------------------------------------------------------------------
extern "C" void kernel_launch(void* const* d_in, const int* in_sizes, int n_in,
                              void* d_out, int out_size) {
    const float* tx = (const float*)d_in[0];   // [T, B, N]
    const float* TE = (const float*)d_in[1];   // [N, T]
    float* out = (float*)d_out;                // [T, B, N]

    (void)in_sizes; (void)n_in; (void)out_size;

    dim3 tb(32, 8);
    dim3 tg(N_DIM / 32, T_STEPS / 32);
    telif_transpose_te<<<tg, tb>>>(TE);

    telif_scan<<<GRID, BLKT>>>(tx, out);
}

// round 13
// speedup vs baseline: 1.0250x; 1.0250x over previous
#include <cuda_runtime.h>
#include <cuda_bf16.h>
#include <cstdint>

// TELIF: temporal-encoded LIF spiking neuron scan.
// tx: [T, B, N] f32, TE: [N, T] f32 -> ty: [T, B, N] f32.
//
// R13 = R11 (best: 53.4us, scan 39.5 @ 69.4% DRAM; 2 producer warps +
// 1 float2 consumer warp per 64 neurons) with per-chunk overhead halved:
//  - CHUNK 16 / STAGES 3 / LAG 2 (same 24KB smem, same in-flight depth,
//    half the barrier/commit/loop cost per byte).
//  - Bit-exact select form for the v update (y is exactly 0 or 1).
//  - __stcs streaming stores for the never-re-read output.
// R12's 16-lane float4 consumer (compute-issue bound) is reverted.

#define T_STEPS 512
#define B_DIM   64
#define N_DIM   1024
#define BN      (B_DIM * N_DIM)

#define REST      0.0f
#define DECAY     0.2f
#define THRESHOLD 0.3f
#define BETA      0.02f

#define CHUNK    16                   // time steps per stage
#define NCHUNK   (T_STEPS / CHUNK)    // 32
#define STAGES   3
#define LAG      2                    // commit-group completion lag
#define HALVES   2                    // producer warps (32 neurons each)
#define BLKT     96                   // warps 0,1 = producers; warp 2 = consumer
#define GRID     (BN / 64)            // 1024 blocks, 64 neurons each

__device__ float g_te_t[T_STEPS * N_DIM];   // TE transposed to [T][N]

// ---------------------------------------------------------------------------
// Transpose TE [N, T] -> g_te_t [T, N]. 32x32 tiles, padded smem.
// ---------------------------------------------------------------------------
__global__ void telif_transpose_te(const float* __restrict__ TE) {
    __shared__ float tile[32][33];
    int n0 = blockIdx.x * 32;
    int t0 = blockIdx.y * 32;
    int lx = threadIdx.x;
    int ly = threadIdx.y;

#pragma unroll
    for (int i = 0; i < 32; i += 8)
        tile[ly + i][lx] = TE[(size_t)(n0 + ly + i) * T_STEPS + (t0 + lx)];
    __syncthreads();
#pragma unroll
    for (int i = 0; i < 32; i += 8)
        g_te_t[(size_t)(t0 + ly + i) * N_DIM + (n0 + lx)] = tile[lx][ly + i];
}

// ---------------------------------------------------------------------------
// PTX helpers
// ---------------------------------------------------------------------------
__device__ __forceinline__ uint32_t smem_u32(const void* p) {
    return (uint32_t)__cvta_generic_to_shared(p);
}
__device__ __forceinline__ void cp_async16(uint32_t saddr, const void* gptr) {
    asm volatile("cp.async.cg.shared.global [%0], [%1], 16;\n"
                 :: "r"(saddr), "l"(gptr));
}
__device__ __forceinline__ void cp_commit() {
    asm volatile("cp.async.commit_group;\n");
}
__device__ __forceinline__ void cp_wait_lag() {
    asm volatile("cp.async.wait_group 2;\n" ::: "memory");
}
__device__ __forceinline__ void cp_wait_all() {
    asm volatile("cp.async.wait_group 0;\n" ::: "memory");
}
__device__ __forceinline__ void mbar_init(uint32_t a, uint32_t cnt) {
    asm volatile("mbarrier.init.shared.b64 [%0], %1;\n" :: "r"(a), "r"(cnt) : "memory");
}
__device__ __forceinline__ void mbar_arrive(uint32_t a) {
    asm volatile("mbarrier.arrive.release.cta.shared::cta.b64 _, [%0];\n"
                 :: "r"(a) : "memory");
}
__device__ __forceinline__ void mbar_wait(uint32_t a, uint32_t phase) {
    uint32_t done;
    asm volatile(
        "{\n\t.reg .pred p;\n\t"
        "mbarrier.try_wait.parity.acquire.cta.shared::cta.b64 p, [%1], %2;\n\t"
        "selp.b32 %0, 1, 0, p;\n\t}"
        : "=r"(done) : "r"(a), "r"(phase) : "memory");
    if (!done) {
        asm volatile(
            "{\n\t.reg .pred P1;\n\t"
            "WL_%=:\n\t"
            "mbarrier.try_wait.parity.acquire.cta.shared::cta.b64 P1, [%0], %1;\n\t"
            "@P1 bra.uni WD_%=;\n\t"
            "bra.uni WL_%=;\n\t"
            "WD_%=:\n\t}"
            :: "r"(a), "r"(phase) : "memory");
    }
}
__device__ __forceinline__ void stcs64(float* gptr, float2 val) {
    asm volatile("st.global.cs.v2.f32 [%0], {%1, %2};\n"
                 :: "l"(gptr), "f"(val.x), "f"(val.y) : "memory");
}

// ---------------------------------------------------------------------------
// Main scan: per block 64 neurons = 2 producer warps + 1 float2 consumer warp.
// smem stage layout: [half][stage][arr(tx=0,te=1)][step][lane32]
// ---------------------------------------------------------------------------
__global__ void __launch_bounds__(BLKT)
telif_scan(const float* __restrict__ tx, float* __restrict__ out) {
    __shared__ __align__(16) float stg[HALVES][STAGES][2][CHUNK][32];
    __shared__ __align__(8)  uint64_t mb_full[HALVES][STAGES];
    __shared__ __align__(8)  uint64_t mb_empty[HALVES][STAGES];

    const int tid  = threadIdx.x;
    const int wid  = tid >> 5;
    const int lane = tid & 31;
    const int blockbase = blockIdx.x * 64;        // first (b*N+n) of block

    if (tid == 0) {
#pragma unroll
        for (int h = 0; h < HALVES; h++)
#pragma unroll
            for (int s = 0; s < STAGES; s++) {
                mbar_init(smem_u32(&mb_full[h][s]), 32);
                mbar_init(smem_u32(&mb_empty[h][s]), 32);
            }
    }
    __syncthreads();

    if (wid < HALVES) {
        // ------------------ producer warp: pure memory pump ------------------
        const int p = wid;
        const int pairbase = blockbase + p * 32;
        const float* txb = tx + pairbase;
        const float* teb = g_te_t + (pairbase & (N_DIM - 1));

        // cp.async split: k = lane + 32j (j=0..3) -> step st = k>>3,
        // 16B segment sg = (k&7)*4 floats. 8 lanes cover one 128B step-row.
        int stj[4], sgj[4];
#pragma unroll
        for (int j = 0; j < 4; j++) {
            int k  = lane + 32 * j;
            stj[j] = k >> 3;
            sgj[j] = (k & 7) * 4;
        }

        int es = 0, eph = 1;     // empty-wait cursor
        int as = 0;              // full-arrive cursor (lags by LAG)

#pragma unroll 1
        for (int c = 0; c < NCHUNK; c++) {
            mbar_wait(smem_u32(&mb_empty[p][es]), eph);

            const float* ctx = txb + (size_t)(c * CHUNK) * BN;
            const float* cte = teb + (size_t)(c * CHUNK) * N_DIM;
#pragma unroll
            for (int j = 0; j < 4; j++) {
                cp_async16(smem_u32(&stg[p][es][0][stj[j]][sgj[j]]),
                           ctx + (size_t)stj[j] * BN + sgj[j]);
                cp_async16(smem_u32(&stg[p][es][1][stj[j]][sgj[j]]),
                           cte + (size_t)stj[j] * N_DIM + sgj[j]);
            }
            cp_commit();

            if (c >= LAG) {
                cp_wait_lag();                       // group c-LAG complete
                mbar_arrive(smem_u32(&mb_full[p][as]));
                if (++as == STAGES) as = 0;
            }
            if (++es == STAGES) { es = 0; eph ^= 1; }
        }
        // Tail: flush last LAG chunks.
        cp_wait_all();
#pragma unroll
        for (int r = 0; r < LAG; r++) {
            mbar_arrive(smem_u32(&mb_full[p][as]));
            if (++as == STAGES) as = 0;
        }
    } else {
        // -------------- consumer warp: 2 neurons per lane (float2) ----------
        const int h  = lane >> 4;
        const int j2 = (2 * lane) & 31;
        float* op = out + blockbase + 2 * lane;     // float2-aligned

        float2 v  = make_float2(REST, REST);
        float2 th = make_float2(THRESHOLD, THRESHOLD);
        bool   px = false, py = false;              // spike predicates (y==1)

        int fs = 0, fph = 0;     // full-wait cursor

#pragma unroll 1
        for (int c = 0; c < NCHUNK; c++) {
            mbar_wait(smem_u32(&mb_full[0][fs]), fph);
            mbar_wait(smem_u32(&mb_full[1][fs]), fph);

            // 4 sub-batches of 4 steps (keeps buffer regs bounded).
#pragma unroll
            for (int g = 0; g < CHUNK / 4; g++) {
                float2 xr[4], tr[4];
#pragma unroll
                for (int s = 0; s < 4; s++) {
                    xr[s] = *reinterpret_cast<const float2*>(&stg[h][fs][0][g * 4 + s][j2]);
                    tr[s] = *reinterpret_cast<const float2*>(&stg[h][fs][1][g * 4 + s][j2]);
                }
#pragma unroll
                for (int s = 0; s < 4; s++) {
                    // th update (expression identical to reference)
                    th.x = th.x + v.x * tr[s].x - (th.x - THRESHOLD) * BETA;
                    th.y = th.y + v.y * tr[s].y - (th.y - THRESHOLD) * BETA;
                    // v = v*DECAY*(1-y)+x, bit-exact via select (y in {0,1})
                    v.x = px ? xr[s].x : v.x * DECAY + xr[s].x;
                    v.y = py ? xr[s].y : v.y * DECAY + xr[s].y;
                    px = (v.x > th.x);
                    py = (v.y > th.y);
                    float2 ys;
                    ys.x = px ? 1.0f : 0.0f;
                    ys.y = py ? 1.0f : 0.0f;
                    stcs64(op + (size_t)(c * CHUNK + g * 4 + s) * BN, ys);
                }
            }

            mbar_arrive(smem_u32(&mb_empty[0][fs]));
            mbar_arrive(smem_u32(&mb_empty[1][fs]));
            if (++fs == STAGES) { fs = 0; fph ^= 1; }
        }
    }
}

// ---------------------------------------------------------------------------
// Launch
// ---------------------------------------------------------------------------
extern "C" void kernel_launch(void* const* d_in, const int* in_sizes, int n_in,
                              void* d_out, int out_size) {
    const float* tx = (const float*)d_in[0];   // [T, B, N]
    const float* TE = (const float*)d_in[1];   // [N, T]
    float* out = (float*)d_out;                // [T, B, N]

    (void)in_sizes; (void)n_in; (void)out_size;

    dim3 tb(32, 8);
    dim3 tg(N_DIM / 32, T_STEPS / 32);
    telif_transpose_te<<<tg, tb>>>(TE);

    telif_scan<<<GRID, BLKT>>>(tx, out);
}